// round 1
// baseline (speedup 1.0000x reference)
#include <cuda_runtime.h>

#define NB 8      // images
#define NG 32     // gt per image
#define TR 256    // train rois per image
#define PQ 25     // int(0.1*256)
#define PMAX 65536

// ---------------- scratch (static device globals; no allocations) -----------
__device__ unsigned int  g_best[PMAX];     // tied-argmax bitmask per proposal
__device__ unsigned char g_info[PMAX];     // img (low 4b) | cls<<4 (0 none,1 pos,2 neg)
__device__ int g_cnt [2 * NB * NG];        // [type][img][g] candidate counts
__device__ int g_need[2 * NB * NG];        // entries this (type,img,g) contributes
__device__ int g_base[2 * NB * NG];        // first output slot for this group
__device__ int g_slots[NB * TR];           // -1 invalid, else p | g<<16 | pos<<21

// ---------------- K0: reset scratch (graph replays!) ------------------------
__global__ void k_init() {
    int t = blockIdx.x * blockDim.x + threadIdx.x;
    if (t < 2 * NB * NG) g_cnt[t] = 0;
    if (t < NB * TR)     g_slots[t] = -1;
}

// ---------------- K1: per-proposal IoU vs own image's 32 GTs -----------------
__global__ void k_classify(const float* __restrict__ prop,
                           const int*   __restrict__ bidx,
                           const float* __restrict__ gt, int P) {
    __shared__ float s_gt[NB * NG * 6];
    __shared__ float s_v1[NB * NG];
    __shared__ int   s_cnt[2 * NB * NG];
    for (int i = threadIdx.x; i < NB * NG * 6; i += blockDim.x) s_gt[i] = gt[i];
    for (int i = threadIdx.x; i < 2 * NB * NG; i += blockDim.x) s_cnt[i] = 0;
    __syncthreads();
    for (int i = threadIdx.x; i < NB * NG; i += blockDim.x) {
        const float* b = &s_gt[i * 6];
        s_v1[i] = __fmul_rn(__fmul_rn(__fsub_rn(b[3], b[0]),
                                      __fsub_rn(b[4], b[1])),
                            __fsub_rn(b[5], b[2]));
    }
    __syncthreads();

    int p = blockIdx.x * blockDim.x + threadIdx.x;
    if (p < P) {
        int img = bidx[p];
        float p0 = prop[p*6+0], p1 = prop[p*6+1], p2 = prop[p*6+2];
        float p3 = prop[p*6+3], p4 = prop[p*6+4], p5 = prop[p*6+5];
        float v2 = __fmul_rn(__fmul_rn(__fsub_rn(p3, p0), __fsub_rn(p4, p1)),
                             __fsub_rn(p5, p2));
        float iou[NG];
        float m = -1.0f;
        #pragma unroll
        for (int g = 0; g < NG; g++) {
            const float* b = &s_gt[(img * NG + g) * 6];
            float l0 = fmaxf(b[0], p0), l1 = fmaxf(b[1], p1), l2 = fmaxf(b[2], p2);
            float h0 = fminf(b[3], p3), h1 = fminf(b[4], p4), h2 = fminf(b[5], p5);
            float d0 = fmaxf(__fsub_rn(h0, l0), 0.0f);
            float d1 = fmaxf(__fsub_rn(h1, l1), 0.0f);
            float d2 = fmaxf(__fsub_rn(h2, l2), 0.0f);
            float inter = __fmul_rn(__fmul_rn(d0, d1), d2);
            float den = __fadd_rn(__fsub_rn(__fadd_rn(s_v1[img * NG + g], v2), inter),
                                  1e-8f);
            float v = __fdiv_rn(inter, den);
            iou[g] = v;
            m = fmaxf(m, v);
        }
        unsigned mask = 0u;
        #pragma unroll
        for (int g = 0; g < NG; g++) mask |= (iou[g] == m) ? (1u << g) : 0u;
        int cls = (m >= 0.5f) ? 1 : ((m < 0.02f) ? 2 : 0);
        g_info[p] = (unsigned char)(img | (cls << 4));
        g_best[p] = cls ? mask : 0u;
        if (cls) {
            int t = cls - 1;
            unsigned mm = mask;
            while (mm) {
                int g = __ffs(mm) - 1;
                mm &= mm - 1;
                atomicAdd(&s_cnt[(t * NB + img) * NG + g], 1);
            }
        }
    }
    __syncthreads();
    for (int i = threadIdx.x; i < 2 * NB * NG; i += blockDim.x) {
        int v = s_cnt[i];
        if (v) atomicAdd(&g_cnt[i], v);
    }
}

// ---------------- K2: quotas and per-(img,g) needed/base ---------------------
__global__ void k_quota() {
    int i = threadIdx.x;
    if (i >= NB) return;
    int ptot = 0, ntot = 0;
    for (int g = 0; g < NG; g++) {
        ptot += g_cnt[(0 * NB + i) * NG + g];
        ntot += g_cnt[(1 * NB + i) * NG + g];
    }
    int pn = min(PQ, ptot);
    int nn = min(TR - pn, ntot);
    int acc = 0;
    for (int g = 0; g < NG; g++) {
        int c = g_cnt[(0 * NB + i) * NG + g];
        int st = min(acc, pn);
        int nd = max(0, min(c, pn - st));
        g_need[(0 * NB + i) * NG + g] = nd;
        g_base[(0 * NB + i) * NG + g] = i * TR + st;
        acc += c;
    }
    acc = 0;
    for (int g = 0; g < NG; g++) {
        int c = g_cnt[(1 * NB + i) * NG + g];
        int st = min(acc, nn);
        int nd = max(0, min(c, nn - st));
        g_need[(1 * NB + i) * NG + g] = nd;
        g_base[(1 * NB + i) * NG + g] = i * TR + pn + st;
        acc += c;
    }
}

// ---------------- K3: ordered first-k compaction per (type,img,g) ------------
__global__ void k_select(int P) {
    int g = blockIdx.x, img = blockIdx.y, t = blockIdx.z;
    int idx = (t * NB + img) * NG + g;
    int needed = g_need[idx];
    if (!needed) return;
    int base = g_base[idx];
    int clsW = t + 1;
    __shared__ int wsum[8];           // blockDim = 256 -> 8 warps
    int lane = threadIdx.x & 31, wid = threadIdx.x >> 5;
    int payload_hi = (g << 16) | ((t == 0) ? (1 << 21) : 0);
    int collected = 0;
    for (int p0 = 0; p0 < P; p0 += blockDim.x) {
        int p = p0 + threadIdx.x;
        bool match = false;
        if (p < P) {
            int inf = g_info[p];
            match = ((inf & 15) == img) && ((inf >> 4) == clsW) &&
                    ((g_best[p] >> g) & 1u);
        }
        unsigned bal = __ballot_sync(0xffffffffu, match);
        if (lane == 0) wsum[wid] = __popc(bal);
        __syncthreads();
        int woff = 0, total = 0;
        #pragma unroll
        for (int w = 0; w < 8; w++) {
            int c = wsum[w];
            woff += (w < wid) ? c : 0;
            total += c;
        }
        if (match) {
            int r = collected + woff + __popc(bal & ((1u << lane) - 1u));
            if (r < needed) g_slots[base + r] = p | payload_hi;
        }
        collected += total;
        __syncthreads();
        if (collected >= needed) break;   // uniform across block
    }
}

// ---------------- K4: gather, regression targets, pack output ----------------
__global__ void k_final(const float* __restrict__ prop,
                        const float* __restrict__ gt,
                        const int*   __restrict__ lab,
                        float* __restrict__ out, int N) {
    int s = blockIdx.x * blockDim.x + threadIdx.x;
    if (s >= N) return;
    int rec = g_slots[s];
    float r[6] = {0, 0, 0, 0, 0, 0};
    float d[6] = {0, 0, 0, 0, 0, 0};
    float lb = 0.0f, tg = 0.0f, ri = -1.0f;
    if (rec >= 0) {
        int p = rec & 0xFFFF;
        int g = (rec >> 16) & 31;
        int ispos = (rec >> 21) & 1;
        int img = s / TR;
        #pragma unroll
        for (int k = 0; k < 6; k++) r[k] = prop[p * 6 + k];
        const float* b = &gt[(img * NG + g) * 6];
        #pragma unroll
        for (int k = 0; k < 3; k++) {
            float sz  = __fsub_rn(r[3 + k], r[k]);
            float ct  = __fmul_rn(__fadd_rn(r[k], r[3 + k]), 0.5f);
            float gsz = __fsub_rn(b[3 + k], b[k]);
            float gct = __fmul_rn(__fadd_rn(b[k], b[3 + k]), 0.5f);
            d[k]     = __fdiv_rn(__fsub_rn(gct, ct), sz);
            d[3 + k] = logf(__fdiv_rn(gsz, sz));
        }
        lb = ispos ? (float)lab[img * NG + g] : 0.0f;
        tg = ispos ? 1.0f : -1.0f;
        ri = (float)img;
    }
    #pragma unroll
    for (int k = 0; k < 6; k++) {
        out[s * 6 + k]         = r[k];
        out[N * 6 + s * 6 + k] = d[k];
    }
    out[N * 12 + s] = lb;
    out[N * 13 + s] = tg;
    out[N * 14 + s] = ri;
}

// ---------------- launcher ---------------------------------------------------
extern "C" void kernel_launch(void* const* d_in, const int* in_sizes, int n_in,
                              void* d_out, int out_size) {
    const float* prop = (const float*)d_in[0];   // [P,6]
    const int*   bidx = (const int*)  d_in[1];   // [P]
    const float* gt   = (const float*)d_in[2];   // [B,G,6]
    const int*   lab  = (const int*)  d_in[3];   // [B,G]
    float* out = (float*)d_out;
    int P = in_sizes[0] / 6;
    if (P > PMAX) P = PMAX;
    const int N = NB * TR;

    k_init<<<(NB * TR + 255) / 256, 256>>>();
    k_classify<<<(P + 255) / 256, 256>>>(prop, bidx, gt, P);
    k_quota<<<1, 32>>>();
    dim3 gsel(NG, NB, 2);
    k_select<<<gsel, 256>>>(P);
    k_final<<<(N + 255) / 256, 256>>>(prop, gt, lab, out, N);
}

// round 2
// speedup vs baseline: 3.1862x; 3.1862x over previous
#include <cuda_runtime.h>

#define NB 8       // images
#define NG 32      // gt per image
#define TR 256     // train rois per image
#define PQ 25      // int(0.1*256)
#define PMAX 65536
#define NCH 256    // proposal chunks of 256
#define NGR (2 * NB * NG)   // 512 groups: [type][img][g]

// ---------------- scratch (static device globals; no allocations) -----------
__device__ unsigned int  g_best[PMAX];        // tied-argmax bitmask per proposal
__device__ unsigned char g_info[PMAX];        // img | cls<<4  (cls: 0 none,1 pos,2 neg)
__device__ int g_chunk_cnt[NGR * NCH];        // [group][chunk] candidate counts
__device__ int g_need[NGR];                   // entries this group contributes
__device__ int g_base[NGR];                   // first output slot for this group
__device__ int g_slots[NB * TR];              // -1 invalid, else p | g<<16 | pos<<21

// ---------------- K0: reset scratch (graph replays!) ------------------------
__global__ void k_init() {
    int t = blockIdx.x * blockDim.x + threadIdx.x;
    if (t < NGR * NCH) g_chunk_cnt[t] = 0;
    if (t < NB * TR)   g_slots[t] = -1;
}

// ---------------- K1: per-proposal IoU vs own image's 32 GTs -----------------
// smem gt layout: image stride 260 floats (260 % 32 == 4 -> 8 images hit 8
// distinct banks), box stride 8, v1 cached at slot 6.
#define IMG_STRIDE 260
__global__ void k_classify(const float* __restrict__ prop,
                           const int*   __restrict__ bidx,
                           const float* __restrict__ gt, int P) {
    __shared__ float s_gt[NB * IMG_STRIDE];
    __shared__ int   s_cnt[NGR];
    for (int i = threadIdx.x; i < NB * NG; i += blockDim.x) {
        int img = i >> 5, g = i & 31;
        float b0 = gt[i*6+0], b1 = gt[i*6+1], b2 = gt[i*6+2];
        float b3 = gt[i*6+3], b4 = gt[i*6+4], b5 = gt[i*6+5];
        float* s = &s_gt[img * IMG_STRIDE + g * 8];
        s[0] = b0; s[1] = b1; s[2] = b2; s[3] = b3; s[4] = b4; s[5] = b5;
        s[6] = __fmul_rn(__fmul_rn(__fsub_rn(b3, b0), __fsub_rn(b4, b1)),
                         __fsub_rn(b5, b2));
    }
    for (int i = threadIdx.x; i < NGR; i += blockDim.x) s_cnt[i] = 0;
    __syncthreads();

    int p = blockIdx.x * blockDim.x + threadIdx.x;
    if (p < P) {
        int img = bidx[p];
        float p0 = prop[p*6+0], p1 = prop[p*6+1], p2 = prop[p*6+2];
        float p3 = prop[p*6+3], p4 = prop[p*6+4], p5 = prop[p*6+5];
        float v2 = __fmul_rn(__fmul_rn(__fsub_rn(p3, p0), __fsub_rn(p4, p1)),
                             __fsub_rn(p5, p2));
        const float* sg = &s_gt[img * IMG_STRIDE];
        float iou[NG];
        float m = -1.0f;
        #pragma unroll
        for (int g = 0; g < NG; g++) {
            const float* b = &sg[g * 8];
            float l0 = fmaxf(b[0], p0), l1 = fmaxf(b[1], p1), l2 = fmaxf(b[2], p2);
            float h0 = fminf(b[3], p3), h1 = fminf(b[4], p4), h2 = fminf(b[5], p5);
            float d0 = fmaxf(__fsub_rn(h0, l0), 0.0f);
            float d1 = fmaxf(__fsub_rn(h1, l1), 0.0f);
            float d2 = fmaxf(__fsub_rn(h2, l2), 0.0f);
            float inter = __fmul_rn(__fmul_rn(d0, d1), d2);
            float den = __fadd_rn(__fsub_rn(__fadd_rn(b[6], v2), inter), 1e-8f);
            float v = __fdiv_rn(inter, den);
            iou[g] = v;
            m = fmaxf(m, v);
        }
        unsigned mask = 0u;
        #pragma unroll
        for (int g = 0; g < NG; g++) mask |= (iou[g] == m) ? (1u << g) : 0u;
        int cls = (m >= 0.5f) ? 1 : ((m < 0.02f) ? 2 : 0);
        g_info[p] = (unsigned char)(img | (cls << 4));
        g_best[p] = cls ? mask : 0u;
        if (cls) {
            int t = cls - 1;
            unsigned mm = mask;
            while (mm) {
                int g = __ffs(mm) - 1;
                mm &= mm - 1;
                atomicAdd(&s_cnt[(t * NB + img) * NG + g], 1);
            }
        }
    }
    __syncthreads();
    // this block IS chunk blockIdx.x: write nonzero counts (init pre-zeroed)
    for (int i = threadIdx.x; i < NGR; i += blockDim.x) {
        int v = s_cnt[i];
        if (v) g_chunk_cnt[i * NCH + blockIdx.x] = v;
    }
}

// ---------------- K2: per-group totals -> quotas -> needed/base --------------
__global__ void k_quota() {
    int img = blockIdx.x;                 // 8 blocks
    __shared__ int s_tot[2 * NG];         // [t*32+g]
    int lane = threadIdx.x & 31, wid = threadIdx.x >> 5;
    for (int grp = wid; grp < 2 * NG; grp += 8) {   // 8 warps
        int t = grp >> 5, g = grp & 31;
        const int* row = &g_chunk_cnt[((t * NB + img) * NG + g) * NCH];
        int sum = 0;
        #pragma unroll
        for (int c = lane; c < NCH; c += 32) sum += row[c];
        #pragma unroll
        for (int o = 16; o; o >>= 1) sum += __shfl_down_sync(0xffffffffu, sum, o);
        if (lane == 0) s_tot[grp] = sum;
    }
    __syncthreads();
    if (threadIdx.x == 0) {
        int ptot = 0, ntot = 0;
        for (int g = 0; g < NG; g++) { ptot += s_tot[g]; ntot += s_tot[NG + g]; }
        int pn = min(PQ, ptot);
        int nn = min(TR - pn, ntot);
        int acc = 0;
        for (int g = 0; g < NG; g++) {
            int c = s_tot[g];
            int st = min(acc, pn);
            int nd = max(0, min(c, pn - st));
            g_need[(0 * NB + img) * NG + g] = nd;
            g_base[(0 * NB + img) * NG + g] = img * TR + st;
            acc += c;
        }
        acc = 0;
        for (int g = 0; g < NG; g++) {
            int c = s_tot[NG + g];
            int st = min(acc, nn);
            int nd = max(0, min(c, nn - st));
            g_need[(1 * NB + img) * NG + g] = nd;
            g_base[(1 * NB + img) * NG + g] = img * TR + pn + st;
            acc += c;
        }
    }
}

// ---------------- K3: scan chunk counts, warps fill active chunks ------------
__global__ void k_select(int P) {
    int g = blockIdx.x, img = blockIdx.y, t = blockIdx.z;
    int gi = (t * NB + img) * NG + g;
    int needed = g_need[gi];
    if (!needed) return;
    int base = g_base[gi];
    int tid = threadIdx.x, lane = tid & 31, wid = tid >> 5;

    // block exclusive scan over the 256 chunk counts of this group
    int cnt = g_chunk_cnt[gi * NCH + tid];
    int x = cnt;
    #pragma unroll
    for (int o = 1; o < 32; o <<= 1) {
        int y = __shfl_up_sync(0xffffffffu, x, o);
        if (lane >= o) x += y;
    }
    __shared__ int wtot[8];
    if (lane == 31) wtot[wid] = x;
    __syncthreads();
    int woff = 0;
    #pragma unroll
    for (int w = 0; w < 8; w++) woff += (w < wid) ? wtot[w] : 0;
    int excl = x + woff - cnt;               // this chunk's output base

    // ordered compaction of active chunks into smem list
    bool active = (cnt > 0) && (excl < needed);
    unsigned abal = __ballot_sync(0xffffffffu, active);
    __shared__ int wact[8];
    if (lane == 0) wact[wid] = __popc(abal);
    __syncthreads();
    int aoff = 0, atot = 0;
    #pragma unroll
    for (int w = 0; w < 8; w++) {
        int c = wact[w];
        aoff += (w < wid) ? c : 0;
        atot += c;
    }
    __shared__ int s_chunk[NCH];
    __shared__ int s_cbase[NCH];
    if (active) {
        int r = aoff + __popc(abal & ((1u << lane) - 1u));
        s_chunk[r] = tid;
        s_cbase[r] = excl;
    }
    __syncthreads();

    // warps independently process active chunks (order preserved via known bases)
    int want = img | ((t + 1) << 4);
    int payload_hi = (g << 16) | ((t == 0) ? (1 << 21) : 0);
    for (int a = wid; a < atot; a += 8) {
        int pbase = s_chunk[a] << 8;
        int run = s_cbase[a];
        #pragma unroll
        for (int r = 0; r < 8; r++) {
            int p = pbase + r * 32 + lane;
            bool match = false;
            if (p < P)
                match = (g_info[p] == want) && ((g_best[p] >> g) & 1u);
            unsigned bal = __ballot_sync(0xffffffffu, match);
            if (match) {
                int rank = run + __popc(bal & ((1u << lane) - 1u));
                if (rank < needed) g_slots[base + rank] = p | payload_hi;
            }
            run += __popc(bal);
        }
    }
}

// ---------------- K4: gather, regression targets, pack output ----------------
__global__ void k_final(const float* __restrict__ prop,
                        const float* __restrict__ gt,
                        const int*   __restrict__ lab,
                        float* __restrict__ out, int N) {
    int s = blockIdx.x * blockDim.x + threadIdx.x;
    if (s >= N) return;
    int rec = g_slots[s];
    float r[6] = {0, 0, 0, 0, 0, 0};
    float d[6] = {0, 0, 0, 0, 0, 0};
    float lb = 0.0f, tg = 0.0f, ri = -1.0f;
    if (rec >= 0) {
        int p = rec & 0xFFFF;
        int g = (rec >> 16) & 31;
        int ispos = (rec >> 21) & 1;
        int img = s / TR;
        #pragma unroll
        for (int k = 0; k < 6; k++) r[k] = prop[p * 6 + k];
        const float* b = &gt[(img * NG + g) * 6];
        #pragma unroll
        for (int k = 0; k < 3; k++) {
            float sz  = __fsub_rn(r[3 + k], r[k]);
            float ct  = __fmul_rn(__fadd_rn(r[k], r[3 + k]), 0.5f);
            float gsz = __fsub_rn(b[3 + k], b[k]);
            float gct = __fmul_rn(__fadd_rn(b[k], b[3 + k]), 0.5f);
            d[k]     = __fdiv_rn(__fsub_rn(gct, ct), sz);
            d[3 + k] = logf(__fdiv_rn(gsz, sz));
        }
        lb = ispos ? (float)lab[img * NG + g] : 0.0f;
        tg = ispos ? 1.0f : -1.0f;
        ri = (float)img;
    }
    #pragma unroll
    for (int k = 0; k < 6; k++) {
        out[s * 6 + k]         = r[k];
        out[N * 6 + s * 6 + k] = d[k];
    }
    out[N * 12 + s] = lb;
    out[N * 13 + s] = tg;
    out[N * 14 + s] = ri;
}

// ---------------- launcher ---------------------------------------------------
extern "C" void kernel_launch(void* const* d_in, const int* in_sizes, int n_in,
                              void* d_out, int out_size) {
    const float* prop = (const float*)d_in[0];   // [P,6]
    const int*   bidx = (const int*)  d_in[1];   // [P]
    const float* gt   = (const float*)d_in[2];   // [B,G,6]
    const int*   lab  = (const int*)  d_in[3];   // [B,G]
    float* out = (float*)d_out;
    int P = in_sizes[0] / 6;
    if (P > PMAX) P = PMAX;
    const int N = NB * TR;

    k_init<<<(NGR * NCH + 255) / 256, 256>>>();
    k_classify<<<(P + 255) / 256, 256>>>(prop, bidx, gt, P);
    k_quota<<<NB, 256>>>();
    dim3 gsel(NG, NB, 2);
    k_select<<<gsel, 256>>>(P);
    k_final<<<(N + 255) / 256, 256>>>(prop, gt, lab, out, N);
}

// round 11
// speedup vs baseline: 3.7719x; 1.1838x over previous
#include <cuda_runtime.h>

#define NB 8       // images
#define NG 32      // gt per image
#define TR 256     // train rois per image
#define PQ 25      // int(0.1*256)
#define PMAX 65536
#define NGR (2 * NB * NG)   // 512 groups: [type][img][g]
#define NOUT (NB * TR)      // 2048 output slots

// ---------------- scratch (static device globals; no allocations) -----------
__device__ unsigned int  g_best[PMAX];             // tied-argmax bitmask per proposal
__device__ unsigned char g_info[PMAX];             // img | cls<<4 (0 none,1 pos,2 neg)
__device__ int g_chunk_cnt[(PMAX / 256) * NGR];    // [chunk][group] counts

// ---------------- K1: per-proposal IoU vs own image's 32 GTs -----------------
// smem gt layout: image stride 260 floats (260 % 32 == 4 -> 8 images on 8
// distinct banks), box stride 8, precomputed gt volume at slot 6.
#define IMG_STRIDE 260
__global__ __launch_bounds__(256)
void k_classify(const float* __restrict__ prop,
                const int*   __restrict__ bidx,
                const float* __restrict__ gt, int P) {
    __shared__ float s_gt[NB * IMG_STRIDE];
    __shared__ int   s_cnt[NGR];
    for (int i = threadIdx.x; i < NB * NG; i += blockDim.x) {
        int img = i >> 5, g = i & 31;
        float b0 = gt[i*6+0], b1 = gt[i*6+1], b2 = gt[i*6+2];
        float b3 = gt[i*6+3], b4 = gt[i*6+4], b5 = gt[i*6+5];
        float* s = &s_gt[img * IMG_STRIDE + g * 8];
        s[0] = b0; s[1] = b1; s[2] = b2; s[3] = b3; s[4] = b4; s[5] = b5;
        s[6] = __fmul_rn(__fmul_rn(__fsub_rn(b3, b0), __fsub_rn(b4, b1)),
                         __fsub_rn(b5, b2));
    }
    for (int i = threadIdx.x; i < NGR; i += blockDim.x) s_cnt[i] = 0;
    __syncthreads();

    int p = blockIdx.x * blockDim.x + threadIdx.x;
    if (p < P) {
        int img = bidx[p];
        const float2* pr = (const float2*)(prop + p * 6);
        float2 a0 = pr[0], a1 = pr[1], a2 = pr[2];
        float p0 = a0.x, p1 = a0.y, p2 = a1.x;
        float p3 = a1.y, p4 = a2.x, p5 = a2.y;
        float v2 = __fmul_rn(__fmul_rn(__fsub_rn(p3, p0), __fsub_rn(p4, p1)),
                             __fsub_rn(p5, p2));
        const float* sg = &s_gt[img * IMG_STRIDE];
        float iou[NG];
        float m = -1.0f;
        #pragma unroll
        for (int g = 0; g < NG; g++) {
            const float* b = &sg[g * 8];
            float l0 = fmaxf(b[0], p0), l1 = fmaxf(b[1], p1), l2 = fmaxf(b[2], p2);
            float h0 = fminf(b[3], p3), h1 = fminf(b[4], p4), h2 = fminf(b[5], p5);
            float d0 = fmaxf(__fsub_rn(h0, l0), 0.0f);
            float d1 = fmaxf(__fsub_rn(h1, l1), 0.0f);
            float d2 = fmaxf(__fsub_rn(h2, l2), 0.0f);
            float inter = __fmul_rn(__fmul_rn(d0, d1), d2);
            float den = __fadd_rn(__fsub_rn(__fadd_rn(b[6], v2), inter), 1e-8f);
            float v = __fdiv_rn(inter, den);
            iou[g] = v;
            m = fmaxf(m, v);
        }
        unsigned mask = 0u;
        #pragma unroll
        for (int g = 0; g < NG; g++) mask |= (iou[g] == m) ? (1u << g) : 0u;
        int cls = (m >= 0.5f) ? 1 : ((m < 0.02f) ? 2 : 0);
        g_info[p] = (unsigned char)(img | (cls << 4));
        g_best[p] = cls ? mask : 0u;
        if (cls) {
            int t = cls - 1;
            unsigned mm = mask;
            while (mm) {
                int g = __ffs(mm) - 1;
                mm &= mm - 1;
                atomicAdd(&s_cnt[(t * NB + img) * NG + g], 1);
            }
        }
    }
    __syncthreads();
    // this block IS chunk blockIdx.x: write full coalesced row (incl zeros)
    for (int i = threadIdx.x; i < NGR; i += blockDim.x)
        g_chunk_cnt[blockIdx.x * NGR + i] = s_cnt[i];
}

// ---------------- slot writer -----------------------------------------------
__device__ __forceinline__ void write_slot(float* __restrict__ out,
                                           const float* __restrict__ prop,
                                           const float* __restrict__ gt,
                                           const int*   __restrict__ lab,
                                           int s, int rec, int img,
                                           int ispos, int valid) {
    float r[6] = {0, 0, 0, 0, 0, 0};
    float d[6] = {0, 0, 0, 0, 0, 0};
    float lb = 0.0f, tg = 0.0f, ri = -1.0f;
    if (valid) {
        int p = rec & 0xFFFF;
        int g = (rec >> 16) & 31;
        #pragma unroll
        for (int k = 0; k < 6; k++) r[k] = prop[p * 6 + k];
        const float* b = &gt[(img * NG + g) * 6];
        #pragma unroll
        for (int k = 0; k < 3; k++) {
            float sz  = __fsub_rn(r[3 + k], r[k]);
            float ct  = __fmul_rn(__fadd_rn(r[k], r[3 + k]), 0.5f);
            float gsz = __fsub_rn(b[3 + k], b[k]);
            float gct = __fmul_rn(__fadd_rn(b[k], b[3 + k]), 0.5f);
            d[k]     = __fdiv_rn(__fsub_rn(gct, ct), sz);
            d[3 + k] = logf(__fdiv_rn(gsz, sz));
        }
        lb = ispos ? (float)lab[img * NG + g] : 0.0f;
        tg = ispos ? 1.0f : -1.0f;
        ri = (float)img;
    }
    #pragma unroll
    for (int k = 0; k < 6; k++) {
        out[s * 6 + k]            = r[k];
        out[NOUT * 6 + s * 6 + k] = d[k];
    }
    out[NOUT * 12 + s] = lb;
    out[NOUT * 13 + s] = tg;
    out[NOUT * 14 + s] = ri;
}

// ---------------- K2: quota + ordered select + finalize, one (img,t) block ---
__global__ __launch_bounds__(256)
void k_selfin(const float* __restrict__ prop,
              const float* __restrict__ gt,
              const int*   __restrict__ lab,
              float* __restrict__ out, int P, int nch) {
    int img = blockIdx.x, t = blockIdx.y;
    int tid = threadIdx.x, lane = tid & 31, wid = tid >> 5;

    __shared__ int s_cnt[NG * 257];      // [g][chunk], pad 257 -> conflict-free
    __shared__ int s_tot[NG];
    __shared__ int s_need[NG], s_lbase[NG];
    __shared__ int s_wtmp[8], s_wact[8];
    __shared__ int s_chunk[256], s_cbase[256];
    __shared__ int s_slot[TR];
    __shared__ int s_quota[2];           // [pn, myquota]

    int grp0 = (t * NB + img) * NG;
    // transposed, coalesced load of this block's 32 group rows
    #pragma unroll
    for (int i = 0; i < 32; i++) {
        int idx = i * 256 + tid;
        int c = idx >> 5, j = idx & 31;
        s_cnt[j * 257 + c] = (c < nch) ? g_chunk_cnt[c * NGR + grp0 + j] : 0;
    }
    // neg blocks also need ptot: sum the pos region on the fly
    int psum = 0;
    if (t == 1) {
        int pg0 = img * NG;
        #pragma unroll
        for (int i = 0; i < 32; i++) {
            int idx = i * 256 + tid;
            int c = idx >> 5, j = idx & 31;
            psum += (c < nch) ? g_chunk_cnt[c * NGR + pg0 + j] : 0;
        }
    }
    __syncthreads();
    // per-group totals: warp w reduces groups w, w+8, w+16, w+24
    for (int g = wid; g < NG; g += 8) {
        int sum = 0;
        #pragma unroll
        for (int c = lane; c < 256; c += 32) sum += s_cnt[g * 257 + c];
        #pragma unroll
        for (int o = 16; o; o >>= 1) sum += __shfl_down_sync(0xffffffffu, sum, o);
        if (lane == 0) s_tot[g] = sum;
    }
    #pragma unroll
    for (int o = 16; o; o >>= 1) psum += __shfl_down_sync(0xffffffffu, psum, o);
    if (lane == 0) s_wtmp[wid] = psum;
    __syncthreads();
    if (tid == 0) {
        int ptot = 0;
        if (t == 1) { for (int w = 0; w < 8; w++) ptot += s_wtmp[w]; }
        else        { for (int g = 0; g < NG; g++) ptot += s_tot[g]; }
        int pn = min(PQ, ptot);
        int quota;
        if (t == 0) quota = pn;
        else {
            int ntot = 0;
            for (int g = 0; g < NG; g++) ntot += s_tot[g];
            quota = min(TR - pn, ntot);
        }
        s_quota[0] = pn;
        s_quota[1] = quota;
        int acc = 0;
        for (int g = 0; g < NG; g++) {
            int c = s_tot[g];
            int st = min(acc, quota);
            s_need[g]  = max(0, min(c, quota - st));
            s_lbase[g] = st;                 // 0-based within this block's region
            acc += c;
        }
    }
    __syncthreads();
    int pn  = s_quota[0];
    int myq = s_quota[1];
    int want = img | ((t + 1) << 4);

    for (int g = 0; g < NG; g++) {
        int need = s_need[g];
        if (!need) continue;                 // uniform across block
        __syncthreads();                     // protect smem reuse vs prev iter
        int lb = s_lbase[g];
        // block exclusive scan of this group's 256 chunk counts
        int cnt = s_cnt[g * 257 + tid];
        int x = cnt;
        #pragma unroll
        for (int o = 1; o < 32; o <<= 1) {
            int y = __shfl_up_sync(0xffffffffu, x, o);
            if (lane >= o) x += y;
        }
        if (lane == 31) s_wtmp[wid] = x;
        __syncthreads();
        int woff = 0;
        #pragma unroll
        for (int w = 0; w < 8; w++) woff += (w < wid) ? s_wtmp[w] : 0;
        int excl = x + woff - cnt;
        // compact active chunks (ordered)
        bool active = (cnt > 0) && (excl < need);
        unsigned abal = __ballot_sync(0xffffffffu, active);
        if (lane == 0) s_wact[wid] = __popc(abal);
        __syncthreads();
        int aoff = 0, atot = 0;
        #pragma unroll
        for (int w = 0; w < 8; w++) {
            int c = s_wact[w];
            aoff += (w < wid) ? c : 0;
            atot += c;
        }
        if (active) {
            int r = aoff + __popc(abal & ((1u << lane) - 1u));
            s_chunk[r] = tid;
            s_cbase[r] = excl;
        }
        __syncthreads();
        // warps fill active chunks independently (bases known up front)
        for (int a = wid; a < atot; a += 8) {
            int pbase = s_chunk[a] << 8;
            int run = s_cbase[a];
            #pragma unroll
            for (int r = 0; r < 8; r++) {
                int p = pbase + r * 32 + lane;
                bool match = (p < P) && (g_info[p] == want) &&
                             ((g_best[p] >> g) & 1u);
                unsigned bal = __ballot_sync(0xffffffffu, match);
                if (match) {
                    int rank = run + __popc(bal & ((1u << lane) - 1u));
                    if (rank < need) s_slot[lb + rank] = p | (g << 16);
                }
                run += __popc(bal);
            }
        }
    }
    __syncthreads();

    // finalize straight out of smem slots
    if (t == 0) {
        if (tid < myq)
            write_slot(out, prop, gt, lab, img * TR + tid, s_slot[tid], img, 1, 1);
    } else {
        if (pn + tid < TR) {
            int valid = tid < myq;
            write_slot(out, prop, gt, lab, img * TR + pn + tid,
                       valid ? s_slot[tid] : 0, img, 0, valid);
        }
    }
}

// ---------------- launcher ---------------------------------------------------
extern "C" void kernel_launch(void* const* d_in, const int* in_sizes, int n_in,
                              void* d_out, int out_size) {
    const float* prop = (const float*)d_in[0];   // [P,6]
    const int*   bidx = (const int*)  d_in[1];   // [P]
    const float* gt   = (const float*)d_in[2];   // [B,G,6]
    const int*   lab  = (const int*)  d_in[3];   // [B,G]
    float* out = (float*)d_out;
    int P = in_sizes[0] / 6;
    if (P > PMAX) P = PMAX;
    int nch = (P + 255) / 256;

    k_classify<<<nch, 256>>>(prop, bidx, gt, P);
    dim3 gsel(NB, 2);
    k_selfin<<<gsel, 256>>>(prop, gt, lab, out, P, nch);
}